// round 16
// baseline (speedup 1.0000x reference)
#include <cuda_runtime.h>
#include <cstdint>

// ---------------------------------------------------------------------------
// SNN: LAYERS [2048,2048,2048,512], B=32, T=100.
// Per-layer big GEMM over all T (M=3200, K=2048) on int8 tensor cores
// (mma.sync m16n8k32 s8 -> s32, EXACT integer accumulation), 3-level nested
// power-of-2 weight quantization (residual <= 2^-27). Levels 2+3 fused in
// one pass via exact in-register x128 rescale. Compile-time specialized
// heavy/light passes (R15 core, untouched). This round: interleaved int2
// I-buffer (single 8B scan load), vectorized encode, merged wsplit for all
// layers, finalize fused into the output scan. 8 launches total.
// ---------------------------------------------------------------------------

#define TT   100
#define BB   32
#define NIN  2048
#define NH   2048
#define NOUT 512
#define MM   (TT * BB)          // 3200
#define KK   2048
#define BM   128
#define BN   128
#define BKB  128                // int8 k-values per chunk (128 bytes/row)
#define NCL  (KK / BKB)         // 16 chunks per level
#define STAGES 3
#define STAGE_BYTES 32768
#define SMEM_BYTES (STAGES * STAGE_BYTES + 1024)

#define SC1  (1.0f / 4096.0f)        // 2^-12  (level 1)
#define SC2  (1.0f / 524288.0f)      // 2^-19  (level 2)
#define SC23 (1.0f / 67108864.0f)    // 2^-26  (combined levels 2+3)

#define NW0  (NH * KK)               // weights per big layer
#define NW2  (NOUT * KK)

// scratch (allocation-free __device__ globals)
__device__ __align__(16) signed char g_S0[MM * NH];       // spikes (s8 {0,1})
__device__ __align__(16) signed char g_S1[MM * NH];
__device__ __align__(16) int2        g_I [MM * NH];       // {acc23, acc1}
__device__ __align__(16) signed char g_Wq[6 * NW0 + 3 * NW2]; // all layers' levels
__device__ unsigned int g_count;
__device__ unsigned int g_done;

// ---------------------------------------------------------------------------
// helpers
// ---------------------------------------------------------------------------
__device__ __forceinline__ uint32_t smem_u32(const void* p) {
    uint32_t a;
    asm("{ .reg .u64 t; cvta.to.shared.u64 t, %1; cvt.u32.u64 %0, t; }"
        : "=r"(a) : "l"(p));
    return a;
}

#define CP_ASYNC16(dst, src) \
    asm volatile("cp.async.cg.shared.global [%0], [%1], 16;\n" :: "r"(dst), "l"(src))
#define CP_COMMIT() asm volatile("cp.async.commit_group;\n" ::: "memory")
#define CP_WAIT1()  asm volatile("cp.async.wait_group 1;\n" ::: "memory")
#define CP_WAIT0()  asm volatile("cp.async.wait_group 0;\n" ::: "memory")

__device__ __forceinline__ void ldsm4(uint32_t& r0, uint32_t& r1,
                                      uint32_t& r2, uint32_t& r3, uint32_t a) {
    asm volatile("ldmatrix.sync.aligned.m8n8.x4.shared.b16 {%0,%1,%2,%3}, [%4];"
                 : "=r"(r0), "=r"(r1), "=r"(r2), "=r"(r3) : "r"(a));
}

__device__ __forceinline__ void imma16832(int* c, const uint32_t* a,
                                          const uint32_t* b) {
    asm volatile(
        "mma.sync.aligned.m16n8k32.row.col.s32.s8.s8.s32 "
        "{%0,%1,%2,%3}, {%4,%5,%6,%7}, {%8,%9}, {%0,%1,%2,%3};"
        : "+r"(c[0]), "+r"(c[1]), "+r"(c[2]), "+r"(c[3])
        : "r"(a[0]), "r"(a[1]), "r"(a[2]), "r"(a[3]), "r"(b[0]), "r"(b[1]));
}

// smem tile: 128 rows x 128B. Swizzle: 16B unit xor low 3 row bits.
__device__ __forceinline__ uint32_t SWZ(uint32_t row, uint32_t unit) {
    return row * 128u + (((unit) ^ (row & 7u)) << 4);
}

// ---------------------------------------------------------------------------
// 1) Poisson encode (float4/char4 vectorized), zeroes counters
// ---------------------------------------------------------------------------
__global__ void encode_kernel(const float* __restrict__ x,
                              const float4* __restrict__ noise4)
{
    if (blockIdx.x == 0 && threadIdx.x == 0) { g_count = 0u; g_done = 0u; }
    int idx = blockIdx.x * blockDim.x + threadIdx.x;
    if (idx < (MM * NIN) / 4) {
        int bi = (idx * 4) % (BB * NIN);
        float4 nz = noise4[idx];
        float4 xv = *(const float4*)(x + bi);
        char4 s;
        s.x = (nz.x < fminf(fmaxf(xv.x, 0.0f), 1.0f)) ? 1 : 0;
        s.y = (nz.y < fminf(fmaxf(xv.y, 0.0f), 1.0f)) ? 1 : 0;
        s.z = (nz.z < fminf(fmaxf(xv.z, 0.0f), 1.0f)) ? 1 : 0;
        s.w = (nz.w < fminf(fmaxf(xv.w, 0.0f), 1.0f)) ? 1 : 0;
        *(char4*)(g_S0 + 4 * idx) = s;
    }
}

// ---------------------------------------------------------------------------
// 2) merged 3-level nested s8 quantization for ALL layers:
//    w = q1*2^-12 + q2*2^-19 + q3*2^-26 + eps, |eps| <= 2^-27.
// ---------------------------------------------------------------------------
__global__ void wsplit_all_kernel(const float* __restrict__ W0,
                                  const float* __restrict__ W1,
                                  const float* __restrict__ W2)
{
    int i = blockIdx.x * blockDim.x + threadIdx.x;
    const float* W;
    signed char* Q;
    int n, k;
    if (i < NW0)               { W = W0; Q = g_Wq;              n = NW0; k = i; }
    else if (i < 2 * NW0)      { W = W1; Q = g_Wq + 3 * NW0;    n = NW0; k = i - NW0; }
    else if (i < 2 * NW0 + NW2){ W = W2; Q = g_Wq + 6 * NW0;    n = NW2; k = i - 2 * NW0; }
    else return;

    float r = W[k];
    float q1 = rintf(r * 4096.0f);     r = fmaf(-q1, SC1, r);
    float q2 = rintf(r * 524288.0f);   r = fmaf(-q2, SC2, r);
    float q3 = rintf(r * 67108864.0f);
    Q[k]         = (signed char)(int)q1;
    Q[n + k]     = (signed char)(int)q2;
    Q[2 * n + k] = (signed char)(int)q3;
}

// ---------------------------------------------------------------------------
// 3) GEMM core, compile-time specialized per pass (unchanged from R15).
// ---------------------------------------------------------------------------
template<int NCH, bool HEAVY>
__device__ __forceinline__ void gemm_core(
    const signed char* __restrict__ Abase,
    const signed char* __restrict__ Wrow,      // level-1 row base
    size_t LVL, uint32_t sb, uint32_t dA,
    int warp_m, int warp_n,
    uint32_t lm_row, uint32_t uhalf, uint32_t rxor,
    int acc[4][4][4])
{
    auto issue = [&](int c) {
        uint32_t st = sb + (uint32_t)(c % STAGES) * STAGE_BYTES;
        const signed char* a_ =
            Abase + (size_t)(HEAVY ? (c & (NCL - 1)) : c) * BKB;
        const signed char* w_ = Wrow +
            (HEAVY ? ((size_t)(1 + (c >> 4)) * LVL +
                      (size_t)(c & (NCL - 1)) * BKB)
                   : (size_t)c * BKB);
#pragma unroll
        for (int i_ = 0; i_ < 4; i_++) {
            CP_ASYNC16(st + dA + (uint32_t)i_ * 4096u,
                       a_ + (size_t)i_ * 32 * KK);
            CP_ASYNC16(st + 16384u + dA + (uint32_t)i_ * 4096u,
                       w_ + (size_t)i_ * 32 * KK);
        }
    };

    issue(0); CP_COMMIT();
    issue(1); CP_COMMIT();

#pragma unroll
    for (int c = 0; c < NCH; c++) {
        CP_WAIT1();
        __syncthreads();
        if (c + 2 < NCH) issue(c + 2);
        CP_COMMIT();

        if (HEAVY && c == NCL) {
#pragma unroll
            for (int i = 0; i < 4; i++)
#pragma unroll
                for (int j = 0; j < 4; j++)
#pragma unroll
                    for (int r = 0; r < 4; r++) acc[i][j][r] *= 128;
        }

        const uint32_t stA = sb + (uint32_t)(c % STAGES) * STAGE_BYTES;
        const uint32_t stW = stA + 16384u;

#pragma unroll
        for (int ks = 0; ks < 4; ks++) {
            const uint32_t su = (((uint32_t)(2 * ks) + uhalf) ^ rxor) << 4;
            uint32_t a[4][4];
#pragma unroll
            for (int i = 0; i < 4; i++)
                ldsm4(a[i][0], a[i][1], a[i][2], a[i][3],
                      stA + ((uint32_t)(warp_m + i * 16) + lm_row) * 128u + su);
            uint32_t b[4][2];
#pragma unroll
            for (int j2 = 0; j2 < 2; j2++) {
                uint32_t q0, q1, q2, q3;
                ldsm4(q0, q1, q2, q3,
                      stW + ((uint32_t)(warp_n + j2 * 16) + lm_row) * 128u + su);
                b[2 * j2][0] = q0; b[2 * j2 + 1][0] = q1;
                b[2 * j2][1] = q2; b[2 * j2 + 1][1] = q3;
            }
#pragma unroll
            for (int i = 0; i < 4; i++)
#pragma unroll
                for (int j = 0; j < 4; j++)
                    imma16832(acc[i][j], a[i], b[j]);
        }
    }
    CP_WAIT0();
}

__global__ __launch_bounds__(256, 2)
void gemm_imma(const signed char* __restrict__ Aall,
               const signed char* __restrict__ Wq,
               int* __restrict__ Cout, int N)
{
    extern __shared__ unsigned char dsmem[];

    const int tid    = threadIdx.x;
    const int lane   = tid & 31;
    const int wid    = tid >> 5;
    const int warp_m = (wid & 1) * 64;
    const int warp_n = (wid >> 1) * 32;
    const int m0     = blockIdx.y * BM;
    const int n0     = blockIdx.x * BN;
    const size_t LVL = (size_t)N * KK;
    const int zo     = (blockIdx.z == 0) ? 0 : 1;   // interleave slot

    const uint32_t sb = (smem_u32(dsmem) + 1023u) & ~1023u;

    const int lrow = tid >> 3;
    const int lu   = tid & 7;
    const uint32_t dA = SWZ((uint32_t)lrow, (uint32_t)lu);
    const signed char* Abase = Aall + (size_t)(m0 + lrow) * KK + lu * 16;
    const signed char* Wrow  = Wq   + (size_t)(n0 + lrow) * KK + lu * 16;

    int acc[4][4][4];
#pragma unroll
    for (int i = 0; i < 4; i++)
#pragma unroll
        for (int j = 0; j < 4; j++)
#pragma unroll
            for (int r = 0; r < 4; r++) acc[i][j][r] = 0;

    const uint32_t lm_row = (uint32_t)(lane & 15);
    const uint32_t uhalf  = (uint32_t)(lane >> 4);
    const uint32_t rxor   = (uint32_t)(lane & 7);

    if (blockIdx.z == 0)
        gemm_core<2 * NCL, true >(Abase, Wrow, LVL, sb, dA,
                                  warp_m, warp_n, lm_row, uhalf, rxor, acc);
    else
        gemm_core<NCL,     false>(Abase, Wrow, LVL, sb, dA,
                                  warp_m, warp_n, lm_row, uhalf, rxor, acc);

    // epilogue: interleaved s32 stores; z=0 -> slot 0 (acc23), z=1 -> slot 1
#pragma unroll
    for (int i = 0; i < 4; i++) {
#pragma unroll
        for (int j = 0; j < 4; j++) {
            int m = m0 + warp_m + i * 16 + (lane >> 2);
            int n = n0 + warp_n + j * 8 + (lane & 3) * 2;
            size_t b0 = 2 * ((size_t)m * N + n) + zo;
            Cout[b0]     = acc[i][j][0];
            Cout[b0 + 2] = acc[i][j][1];
            size_t b1 = 2 * ((size_t)(m + 8) * N + n) + zo;
            Cout[b1]     = acc[i][j][2];
            Cout[b1 + 2] = acc[i][j][3];
        }
    }
}

// ---------------------------------------------------------------------------
// 4) LIF time-scan per (b, n): one int2 load per step {acc23, acc1},
//    combined with exact power-of-2 scales (same fmaf order as before).
// ---------------------------------------------------------------------------
__global__ void lif_scan_kernel(const int2* __restrict__ I2,
                                const float* __restrict__ bias,
                                signed char* __restrict__ Sout, int N)
{
    const int idx = blockIdx.x * blockDim.x + threadIdx.x;   // b*N + n
    const int j = idx & (N - 1);
    const float bj = bias[j];
    const int stride = BB * N;

    float syn = 0.0f, mem = 0.0f;
    int cnt = 0;
#pragma unroll 10
    for (int t = 0; t < TT; t++) {
        int2 v = I2[(size_t)t * stride + idx];
        float Iv = fmaf((float)v.y, SC1, fmaf((float)v.x, SC23, bj));
        syn = syn + (Iv - syn * (1.0f / 5.0f));
        mem = mem + (syn - mem * (1.0f / 20.0f));
        signed char sp;
        if (mem >= 1.0f) { sp = 1; mem = 0.0f; cnt++; }
        else             { sp = 0; if (mem < 0.0f) mem = 0.0f; }
        Sout[(size_t)t * stride + idx] = sp;
    }
    unsigned s = __reduce_add_sync(0xFFFFFFFFu, (unsigned)cnt);
    if ((threadIdx.x & 31) == 0) atomicAdd(&g_count, s);
}

// Output-layer scan: also finalizes the spike-count scalar (last block).
__global__ void lif_scan_out_kernel(const int2* __restrict__ I2,
                                    const float* __restrict__ bias,
                                    float* __restrict__ out, int pos)
{
    __shared__ unsigned int wsum[8];
    const int idx = blockIdx.x * blockDim.x + threadIdx.x;   // b*512 + n
    const int j = idx & (NOUT - 1);
    const float bj = bias[j];
    const int stride = BB * NOUT;

    float syn = 0.0f, mem = 0.0f;
    int cnt = 0;
#pragma unroll 10
    for (int t = 0; t < TT; t++) {
        int2 v = I2[(size_t)t * stride + idx];
        float Iv = fmaf((float)v.y, SC1, fmaf((float)v.x, SC23, bj));
        syn = syn + (Iv - syn * (1.0f / 5.0f));
        mem = mem + (syn - mem * (1.0f / 20.0f));
        if (mem >= 1.0f) { mem = 0.0f; cnt++; }
        else if (mem < 0.0f) mem = 0.0f;
    }
    out[idx] = (float)cnt * (1.0f / (float)TT);

    unsigned s = __reduce_add_sync(0xFFFFFFFFu, (unsigned)cnt);
    if ((threadIdx.x & 31) == 0) wsum[threadIdx.x >> 5] = s;
    __syncthreads();
    if (threadIdx.x == 0) {
        unsigned tot = 0;
#pragma unroll
        for (int w = 0; w < 8; w++) tot += wsum[w];
        atomicAdd(&g_count, tot);
        __threadfence();
        unsigned tk = atomicAdd(&g_done, 1u);
        if (tk == gridDim.x - 1) {
            out[pos] = (float)atomicAdd(&g_count, 0u);
        }
    }
}

// ---------------------------------------------------------------------------
// kernel_launch
// ---------------------------------------------------------------------------
extern "C" void kernel_launch(void* const* d_in, const int* in_sizes, int n_in,
                              void* d_out, int out_size)
{
    const float *x = nullptr, *noise = nullptr;
    const float *W0 = nullptr, *b0 = nullptr, *W1 = nullptr, *b1 = nullptr;
    const float *W2 = nullptr, *b2 = nullptr;

    for (int i = 0; i < n_in; i++) {
        long s = (long)in_sizes[i];
        const float* p = (const float*)d_in[i];
        if      (s == (long)BB * NIN)      x = p;
        else if (s == (long)MM * NIN)      noise = p;
        else if (s == (long)NH * NIN)      { if (!W0) W0 = p; else W1 = p; }
        else if (s == (long)NH)            { if (!b0) b0 = p; else b1 = p; }
        else if (s == (long)NOUT * NH)     W2 = p;
        else if (s == (long)NOUT)          b2 = p;
    }

    cudaFuncSetAttribute(gemm_imma,
                         cudaFuncAttributeMaxDynamicSharedMemorySize,
                         SMEM_BYTES);

    void *pS0, *pS1, *pI, *pQ;
    cudaGetSymbolAddress(&pS0, g_S0);
    cudaGetSymbolAddress(&pS1, g_S1);
    cudaGetSymbolAddress(&pI,  g_I);
    cudaGetSymbolAddress(&pQ,  g_Wq);
    signed char* S0 = (signed char*)pS0;
    signed char* S1 = (signed char*)pS1;
    int*  Ibuf  = (int*)pI;
    int2* Ibuf2 = (int2*)pI;
    signed char* Q = (signed char*)pQ;
    float* out  = (float*)d_out;

    // 1) encode input spikes + zero counters (1 launch)
    encode_kernel<<<(MM * NIN / 4 + 255) / 256, 256>>>(x, (const float4*)noise);

    // 2) quantize all three layers' weights (1 launch)
    wsplit_all_kernel<<<(2 * NW0 + NW2 + 255) / 256, 256>>>(W0, W1, W2);

    // 3) layer 0
    gemm_imma<<<dim3(NH / BN, MM / BM, 2), 256, SMEM_BYTES>>>(S0, Q, Ibuf, NH);
    lif_scan_kernel<<<(BB * NH) / 256, 256>>>(Ibuf2, b0, S1, NH);

    // 4) layer 1
    gemm_imma<<<dim3(NH / BN, MM / BM, 2), 256, SMEM_BYTES>>>(S1, Q + 3 * (size_t)NW0, Ibuf, NH);
    lif_scan_kernel<<<(BB * NH) / 256, 256>>>(Ibuf2, b1, S0, NH);

    // 5) layer 2 (output) + fused spike-count finalize
    gemm_imma<<<dim3(NOUT / BN, MM / BM, 2), 256, SMEM_BYTES>>>(S0, Q + 6 * (size_t)NW0, Ibuf, NOUT);
    lif_scan_out_kernel<<<(BB * NOUT) / 256, 256>>>(Ibuf2, b2, out, out_size - 1);
}

// round 17
// speedup vs baseline: 1.0097x; 1.0097x over previous
#include <cuda_runtime.h>
#include <cstdint>

// ---------------------------------------------------------------------------
// SNN: LAYERS [2048,2048,2048,512], B=32, T=100.
// Per-layer big GEMM over all T (M=3200, K=2048) on int8 tensor cores
// (mma.sync m16n8k32 s8 -> s32, EXACT integer accumulation), 3-level nested
// power-of-2 weight quantization (residual <= 2^-27). Levels 2+3 fused via
// exact in-register x128 rescale. Compile-time specialized passes.
// This round: output-layer GEMM split along K into 2 halves (grid z=4,
// 400 CTAs instead of 200 -> fills the machine); the two s32 halves are
// added EXACTLY (integer) in the output scan, so results are bit-identical.
// ---------------------------------------------------------------------------

#define TT   100
#define BB   32
#define NIN  2048
#define NH   2048
#define NOUT 512
#define MM   (TT * BB)          // 3200
#define KK   2048
#define BM   128
#define BN   128
#define BKB  128                // int8 k-values per chunk (128 bytes/row)
#define NCL  (KK / BKB)         // 16 chunks per level (full K)
#define STAGES 3
#define STAGE_BYTES 32768
#define SMEM_BYTES (STAGES * STAGE_BYTES + 1024)

#define SC1  (1.0f / 4096.0f)        // 2^-12  (level 1)
#define SC2  (1.0f / 524288.0f)      // 2^-19  (level 2)
#define SC23 (1.0f / 67108864.0f)    // 2^-26  (combined levels 2+3)

#define NW0  (NH * KK)               // weights per big layer
#define NW2  (NOUT * KK)

// scratch (allocation-free __device__ globals)
__device__ __align__(16) signed char g_S0[MM * NH];       // spikes (s8 {0,1})
__device__ __align__(16) signed char g_S1[MM * NH];
__device__ __align__(16) int2        g_I [MM * NH];       // {acc23, acc1} / int4 for out
__device__ __align__(16) signed char g_Wq[6 * NW0 + 3 * NW2];
__device__ unsigned int g_count;
__device__ unsigned int g_done;

// ---------------------------------------------------------------------------
// helpers
// ---------------------------------------------------------------------------
__device__ __forceinline__ uint32_t smem_u32(const void* p) {
    uint32_t a;
    asm("{ .reg .u64 t; cvta.to.shared.u64 t, %1; cvt.u32.u64 %0, t; }"
        : "=r"(a) : "l"(p));
    return a;
}

#define CP_ASYNC16(dst, src) \
    asm volatile("cp.async.cg.shared.global [%0], [%1], 16;\n" :: "r"(dst), "l"(src))
#define CP_COMMIT() asm volatile("cp.async.commit_group;\n" ::: "memory")
#define CP_WAIT1()  asm volatile("cp.async.wait_group 1;\n" ::: "memory")
#define CP_WAIT0()  asm volatile("cp.async.wait_group 0;\n" ::: "memory")

__device__ __forceinline__ void ldsm4(uint32_t& r0, uint32_t& r1,
                                      uint32_t& r2, uint32_t& r3, uint32_t a) {
    asm volatile("ldmatrix.sync.aligned.m8n8.x4.shared.b16 {%0,%1,%2,%3}, [%4];"
                 : "=r"(r0), "=r"(r1), "=r"(r2), "=r"(r3) : "r"(a));
}

__device__ __forceinline__ void imma16832(int* c, const uint32_t* a,
                                          const uint32_t* b) {
    asm volatile(
        "mma.sync.aligned.m16n8k32.row.col.s32.s8.s8.s32 "
        "{%0,%1,%2,%3}, {%4,%5,%6,%7}, {%8,%9}, {%0,%1,%2,%3};"
        : "+r"(c[0]), "+r"(c[1]), "+r"(c[2]), "+r"(c[3])
        : "r"(a[0]), "r"(a[1]), "r"(a[2]), "r"(a[3]), "r"(b[0]), "r"(b[1]));
}

// smem tile: 128 rows x 128B. Swizzle: 16B unit xor low 3 row bits.
__device__ __forceinline__ uint32_t SWZ(uint32_t row, uint32_t unit) {
    return row * 128u + (((unit) ^ (row & 7u)) << 4);
}

// ---------------------------------------------------------------------------
// 1) Poisson encode (float4/char4 vectorized), zeroes counters
// ---------------------------------------------------------------------------
__global__ void encode_kernel(const float* __restrict__ x,
                              const float4* __restrict__ noise4)
{
    if (blockIdx.x == 0 && threadIdx.x == 0) { g_count = 0u; g_done = 0u; }
    int idx = blockIdx.x * blockDim.x + threadIdx.x;
    if (idx < (MM * NIN) / 4) {
        int bi = (idx * 4) % (BB * NIN);
        float4 nz = noise4[idx];
        float4 xv = *(const float4*)(x + bi);
        char4 s;
        s.x = (nz.x < fminf(fmaxf(xv.x, 0.0f), 1.0f)) ? 1 : 0;
        s.y = (nz.y < fminf(fmaxf(xv.y, 0.0f), 1.0f)) ? 1 : 0;
        s.z = (nz.z < fminf(fmaxf(xv.z, 0.0f), 1.0f)) ? 1 : 0;
        s.w = (nz.w < fminf(fmaxf(xv.w, 0.0f), 1.0f)) ? 1 : 0;
        *(char4*)(g_S0 + 4 * idx) = s;
    }
}

// ---------------------------------------------------------------------------
// 2) merged 3-level nested s8 quantization for ALL layers:
//    w = q1*2^-12 + q2*2^-19 + q3*2^-26 + eps, |eps| <= 2^-27.
// ---------------------------------------------------------------------------
__global__ void wsplit_all_kernel(const float* __restrict__ W0,
                                  const float* __restrict__ W1,
                                  const float* __restrict__ W2)
{
    int i = blockIdx.x * blockDim.x + threadIdx.x;
    const float* W;
    signed char* Q;
    int n, k;
    if (i < NW0)               { W = W0; Q = g_Wq;              n = NW0; k = i; }
    else if (i < 2 * NW0)      { W = W1; Q = g_Wq + 3 * NW0;    n = NW0; k = i - NW0; }
    else if (i < 2 * NW0 + NW2){ W = W2; Q = g_Wq + 6 * NW0;    n = NW2; k = i - 2 * NW0; }
    else return;

    float r = W[k];
    float q1 = rintf(r * 4096.0f);     r = fmaf(-q1, SC1, r);
    float q2 = rintf(r * 524288.0f);   r = fmaf(-q2, SC2, r);
    float q3 = rintf(r * 67108864.0f);
    Q[k]         = (signed char)(int)q1;
    Q[n + k]     = (signed char)(int)q2;
    Q[2 * n + k] = (signed char)(int)q3;
}

// ---------------------------------------------------------------------------
// 3) GEMM core, compile-time specialized. CPL = chunks per level. choff is a
//    runtime additive chunk offset (K-half base); trip counts stay constant.
//    HEAVY: chunks 0..CPL-1 -> Q2, CPL..2CPL-1 -> Q3, exact x128 rescale
//    between. LIGHT: chunks 0..CPL-1 -> Q1.
// ---------------------------------------------------------------------------
template<int NCH, bool HEAVY, int CPL>
__device__ __forceinline__ void gemm_core(
    const signed char* __restrict__ Abase,
    const signed char* __restrict__ Wrow,      // level-1 row base
    size_t LVL, int choff, uint32_t sb, uint32_t dA,
    int warp_m, int warp_n,
    uint32_t lm_row, uint32_t uhalf, uint32_t rxor,
    int acc[4][4][4])
{
    auto issue = [&](int c) {
        uint32_t st = sb + (uint32_t)(c % STAGES) * STAGE_BYTES;
        const signed char* a_ =
            Abase + (size_t)(choff + (HEAVY ? (c % CPL) : c)) * BKB;
        const signed char* w_ = Wrow +
            (HEAVY ? ((size_t)(1 + (c / CPL)) * LVL +
                      (size_t)(choff + (c % CPL)) * BKB)
                   : (size_t)(choff + c) * BKB);
#pragma unroll
        for (int i_ = 0; i_ < 4; i_++) {
            CP_ASYNC16(st + dA + (uint32_t)i_ * 4096u,
                       a_ + (size_t)i_ * 32 * KK);
            CP_ASYNC16(st + 16384u + dA + (uint32_t)i_ * 4096u,
                       w_ + (size_t)i_ * 32 * KK);
        }
    };

    issue(0); CP_COMMIT();
    issue(1); CP_COMMIT();

#pragma unroll
    for (int c = 0; c < NCH; c++) {
        CP_WAIT1();
        __syncthreads();
        if (c + 2 < NCH) issue(c + 2);
        CP_COMMIT();

        if (HEAVY && c == CPL) {
#pragma unroll
            for (int i = 0; i < 4; i++)
#pragma unroll
                for (int j = 0; j < 4; j++)
#pragma unroll
                    for (int r = 0; r < 4; r++) acc[i][j][r] *= 128;
        }

        const uint32_t stA = sb + (uint32_t)(c % STAGES) * STAGE_BYTES;
        const uint32_t stW = stA + 16384u;

#pragma unroll
        for (int ks = 0; ks < 4; ks++) {
            const uint32_t su = (((uint32_t)(2 * ks) + uhalf) ^ rxor) << 4;
            uint32_t a[4][4];
#pragma unroll
            for (int i = 0; i < 4; i++)
                ldsm4(a[i][0], a[i][1], a[i][2], a[i][3],
                      stA + ((uint32_t)(warp_m + i * 16) + lm_row) * 128u + su);
            uint32_t b[4][2];
#pragma unroll
            for (int j2 = 0; j2 < 2; j2++) {
                uint32_t q0, q1, q2, q3;
                ldsm4(q0, q1, q2, q3,
                      stW + ((uint32_t)(warp_n + j2 * 16) + lm_row) * 128u + su);
                b[2 * j2][0] = q0; b[2 * j2 + 1][0] = q1;
                b[2 * j2][1] = q2; b[2 * j2 + 1][1] = q3;
            }
#pragma unroll
            for (int i = 0; i < 4; i++)
#pragma unroll
                for (int j = 0; j < 4; j++)
                    imma16832(acc[i][j], a[i], b[j]);
        }
    }
    CP_WAIT0();
}

// common per-CTA setup shared by both gemm kernels
struct GemmCtx {
    int warp_m, warp_n, m0, n0, lane;
    uint32_t sb, dA, lm_row, uhalf, rxor;
    const signed char *Abase, *Wrow;
};

__device__ __forceinline__ GemmCtx gemm_setup(
    unsigned char* dsmem, const signed char* Aall, const signed char* Wq)
{
    GemmCtx g;
    const int tid = threadIdx.x;
    g.lane   = tid & 31;
    const int wid = tid >> 5;
    g.warp_m = (wid & 1) * 64;
    g.warp_n = (wid >> 1) * 32;
    g.m0     = blockIdx.y * BM;
    g.n0     = blockIdx.x * BN;
    g.sb     = (smem_u32(dsmem) + 1023u) & ~1023u;
    const int lrow = tid >> 3;
    const int lu   = tid & 7;
    g.dA    = SWZ((uint32_t)lrow, (uint32_t)lu);
    g.Abase = Aall + (size_t)(g.m0 + lrow) * KK + lu * 16;
    g.Wrow  = Wq   + (size_t)(g.n0 + lrow) * KK + lu * 16;
    g.lm_row = (uint32_t)(g.lane & 15);
    g.uhalf  = (uint32_t)(g.lane >> 4);
    g.rxor   = (uint32_t)(g.lane & 7);
    return g;
}

// big layers: full K per CTA, z=0 heavy -> slot 0, z=1 light -> slot 1 (int2)
__global__ __launch_bounds__(256, 2)
void gemm_imma(const signed char* __restrict__ Aall,
               const signed char* __restrict__ Wq,
               int* __restrict__ Cout, int N)
{
    extern __shared__ unsigned char dsmem[];
    GemmCtx g = gemm_setup(dsmem, Aall, Wq);
    const size_t LVL = (size_t)N * KK;
    const int zo = (blockIdx.z == 0) ? 0 : 1;

    int acc[4][4][4];
#pragma unroll
    for (int i = 0; i < 4; i++)
#pragma unroll
        for (int j = 0; j < 4; j++)
#pragma unroll
            for (int r = 0; r < 4; r++) acc[i][j][r] = 0;

    if (blockIdx.z == 0)
        gemm_core<2 * NCL, true,  NCL>(g.Abase, g.Wrow, LVL, 0, g.sb, g.dA,
                                       g.warp_m, g.warp_n, g.lm_row, g.uhalf,
                                       g.rxor, acc);
    else
        gemm_core<NCL,     false, NCL>(g.Abase, g.Wrow, LVL, 0, g.sb, g.dA,
                                       g.warp_m, g.warp_n, g.lm_row, g.uhalf,
                                       g.rxor, acc);

#pragma unroll
    for (int i = 0; i < 4; i++) {
#pragma unroll
        for (int j = 0; j < 4; j++) {
            int m = g.m0 + g.warp_m + i * 16 + (g.lane >> 2);
            int n = g.n0 + g.warp_n + j * 8 + (g.lane & 3) * 2;
            size_t b0 = 2 * ((size_t)m * N + n) + zo;
            Cout[b0]     = acc[i][j][0];
            Cout[b0 + 2] = acc[i][j][1];
            size_t b1 = 2 * ((size_t)(m + 8) * N + n) + zo;
            Cout[b1]     = acc[i][j][2];
            Cout[b1 + 2] = acc[i][j][3];
        }
    }
}

// output layer: K split in 2 halves, z in 0..3: z<2 heavy (kh=z), z>=2 light
// (kh=z-2). int4 slots: heavy khX -> 2X, light khX -> 2X+1.
__global__ __launch_bounds__(256, 2)
void gemm_imma_out(const signed char* __restrict__ Aall,
                   const signed char* __restrict__ Wq,
                   int* __restrict__ Cout)
{
    extern __shared__ unsigned char dsmem[];
    GemmCtx g = gemm_setup(dsmem, Aall, Wq);
    const size_t LVL = (size_t)NOUT * KK;
    const int heavy = (blockIdx.z < 2);
    const int kh    = heavy ? blockIdx.z : (blockIdx.z - 2);
    const int choff = kh * (NCL / 2);
    const int slot  = 2 * kh + (heavy ? 0 : 1);

    int acc[4][4][4];
#pragma unroll
    for (int i = 0; i < 4; i++)
#pragma unroll
        for (int j = 0; j < 4; j++)
#pragma unroll
            for (int r = 0; r < 4; r++) acc[i][j][r] = 0;

    if (heavy)
        gemm_core<NCL,     true,  NCL / 2>(g.Abase, g.Wrow, LVL, choff, g.sb,
                                           g.dA, g.warp_m, g.warp_n, g.lm_row,
                                           g.uhalf, g.rxor, acc);
    else
        gemm_core<NCL / 2, false, NCL / 2>(g.Abase, g.Wrow, LVL, choff, g.sb,
                                           g.dA, g.warp_m, g.warp_n, g.lm_row,
                                           g.uhalf, g.rxor, acc);

#pragma unroll
    for (int i = 0; i < 4; i++) {
#pragma unroll
        for (int j = 0; j < 4; j++) {
            int m = g.m0 + g.warp_m + i * 16 + (g.lane >> 2);
            int n = g.n0 + g.warp_n + j * 8 + (g.lane & 3) * 2;
            size_t b0 = 4 * ((size_t)m * NOUT + n) + slot;
            Cout[b0]     = acc[i][j][0];
            Cout[b0 + 4] = acc[i][j][1];
            size_t b1 = 4 * ((size_t)(m + 8) * NOUT + n) + slot;
            Cout[b1]     = acc[i][j][2];
            Cout[b1 + 4] = acc[i][j][3];
        }
    }
}

// ---------------------------------------------------------------------------
// 4) LIF time-scans
// ---------------------------------------------------------------------------
__global__ void lif_scan_kernel(const int2* __restrict__ I2,
                                const float* __restrict__ bias,
                                signed char* __restrict__ Sout, int N)
{
    const int idx = blockIdx.x * blockDim.x + threadIdx.x;   // b*N + n
    const int j = idx & (N - 1);
    const float bj = bias[j];
    const int stride = BB * N;

    float syn = 0.0f, mem = 0.0f;
    int cnt = 0;
#pragma unroll 10
    for (int t = 0; t < TT; t++) {
        int2 v = I2[(size_t)t * stride + idx];
        float Iv = fmaf((float)v.y, SC1, fmaf((float)v.x, SC23, bj));
        syn = syn + (Iv - syn * (1.0f / 5.0f));
        mem = mem + (syn - mem * (1.0f / 20.0f));
        signed char sp;
        if (mem >= 1.0f) { sp = 1; mem = 0.0f; cnt++; }
        else             { sp = 0; if (mem < 0.0f) mem = 0.0f; }
        Sout[(size_t)t * stride + idx] = sp;
    }
    unsigned s = __reduce_add_sync(0xFFFFFFFFu, (unsigned)cnt);
    if ((threadIdx.x & 31) == 0) atomicAdd(&g_count, s);
}

// Output scan: int4 {acc23_a, acc1_a, acc23_b, acc1_b}; integer half-sums are
// EXACT, then the identical fmaf chain -> bit-identical to unsplit K.
__global__ void lif_scan_out_kernel(const int4* __restrict__ I4,
                                    const float* __restrict__ bias,
                                    float* __restrict__ out, int pos)
{
    __shared__ unsigned int wsum[8];
    const int idx = blockIdx.x * blockDim.x + threadIdx.x;   // b*512 + n
    const int j = idx & (NOUT - 1);
    const float bj = bias[j];
    const int stride = BB * NOUT;

    float syn = 0.0f, mem = 0.0f;
    int cnt = 0;
#pragma unroll 10
    for (int t = 0; t < TT; t++) {
        int4 v = I4[(size_t)t * stride + idx];
        int a23 = v.x + v.z;
        int a1  = v.y + v.w;
        float Iv = fmaf((float)a1, SC1, fmaf((float)a23, SC23, bj));
        syn = syn + (Iv - syn * (1.0f / 5.0f));
        mem = mem + (syn - mem * (1.0f / 20.0f));
        if (mem >= 1.0f) { mem = 0.0f; cnt++; }
        else if (mem < 0.0f) mem = 0.0f;
    }
    out[idx] = (float)cnt * (1.0f / (float)TT);

    unsigned s = __reduce_add_sync(0xFFFFFFFFu, (unsigned)cnt);
    if ((threadIdx.x & 31) == 0) wsum[threadIdx.x >> 5] = s;
    __syncthreads();
    if (threadIdx.x == 0) {
        unsigned tot = 0;
#pragma unroll
        for (int w = 0; w < 8; w++) tot += wsum[w];
        atomicAdd(&g_count, tot);
        __threadfence();
        unsigned tk = atomicAdd(&g_done, 1u);
        if (tk == gridDim.x - 1) {
            out[pos] = (float)atomicAdd(&g_count, 0u);
        }
    }
}

// ---------------------------------------------------------------------------
// kernel_launch
// ---------------------------------------------------------------------------
extern "C" void kernel_launch(void* const* d_in, const int* in_sizes, int n_in,
                              void* d_out, int out_size)
{
    const float *x = nullptr, *noise = nullptr;
    const float *W0 = nullptr, *b0 = nullptr, *W1 = nullptr, *b1 = nullptr;
    const float *W2 = nullptr, *b2 = nullptr;

    for (int i = 0; i < n_in; i++) {
        long s = (long)in_sizes[i];
        const float* p = (const float*)d_in[i];
        if      (s == (long)BB * NIN)      x = p;
        else if (s == (long)MM * NIN)      noise = p;
        else if (s == (long)NH * NIN)      { if (!W0) W0 = p; else W1 = p; }
        else if (s == (long)NH)            { if (!b0) b0 = p; else b1 = p; }
        else if (s == (long)NOUT * NH)     W2 = p;
        else if (s == (long)NOUT)          b2 = p;
    }

    cudaFuncSetAttribute(gemm_imma,
                         cudaFuncAttributeMaxDynamicSharedMemorySize, SMEM_BYTES);
    cudaFuncSetAttribute(gemm_imma_out,
                         cudaFuncAttributeMaxDynamicSharedMemorySize, SMEM_BYTES);

    void *pS0, *pS1, *pI, *pQ;
    cudaGetSymbolAddress(&pS0, g_S0);
    cudaGetSymbolAddress(&pS1, g_S1);
    cudaGetSymbolAddress(&pI,  g_I);
    cudaGetSymbolAddress(&pQ,  g_Wq);
    signed char* S0 = (signed char*)pS0;
    signed char* S1 = (signed char*)pS1;
    int*  Ibuf  = (int*)pI;
    int2* Ibuf2 = (int2*)pI;
    int4* Ibuf4 = (int4*)pI;
    signed char* Q = (signed char*)pQ;
    float* out  = (float*)d_out;

    // 1) encode input spikes + zero counters
    encode_kernel<<<(MM * NIN / 4 + 255) / 256, 256>>>(x, (const float4*)noise);

    // 2) quantize all three layers' weights
    wsplit_all_kernel<<<(2 * NW0 + NW2 + 255) / 256, 256>>>(W0, W1, W2);

    // 3) layer 0
    gemm_imma<<<dim3(NH / BN, MM / BM, 2), 256, SMEM_BYTES>>>(S0, Q, Ibuf, NH);
    lif_scan_kernel<<<(BB * NH) / 256, 256>>>(Ibuf2, b0, S1, NH);

    // 4) layer 1
    gemm_imma<<<dim3(NH / BN, MM / BM, 2), 256, SMEM_BYTES>>>(
        S1, Q + 3 * (size_t)NW0, Ibuf, NH);
    lif_scan_kernel<<<(BB * NH) / 256, 256>>>(Ibuf2, b1, S0, NH);

    // 5) layer 2 (output): K-split GEMM (z=4) + fused finalize scan
    gemm_imma_out<<<dim3(NOUT / BN, MM / BM, 4), 256, SMEM_BYTES>>>(
        S0, Q + 6 * (size_t)NW0, Ibuf);
    lif_scan_out_kernel<<<(BB * NOUT) / 256, 256>>>(Ibuf4, b2, out, out_size - 1);
}